// round 8
// baseline (speedup 1.0000x reference)
#include <cuda_runtime.h>
#include <cuda_bf16.h>
#include <cuda_fp8.h>
#include <stdint.h>

// PINNS IRK fixed-point: 262144 independent rows, 10 iters of 4->128->128->128->4
// tanh MLP. R8 (= R7 resubmit after infra failure): FP8 (e4m3) mma.sync m16n8k32
// for layers 2-4 (half the HMMA count of bf16), activations staged per-warp in
// SMEM as e4m3 (row stride 144B, conflict-free), B-fragments prepacked in
// fragment order (plain LDS.64, no ldmatrix/swizzle). Layer 1 stays bf16 (K=4).
// Block = 4 warps; grid = 2048.

namespace {
constexpr int OFF_W2F = 0;         // 2048 u64: W2 e4m3 frag-packed
constexpr int OFF_W3F = 16384;     // 2048 u64
constexpr int OFF_W4F = 32768;     // 128 u64 (n padded 4->8)
constexpr int OFF_W1  = 33792;     // 128x8 bf16 [n][k pad 4->8]
constexpr int OFF_B1  = 35840;
constexpr int OFF_B2  = 36352;
constexpr int OFF_B3  = 36864;
constexpr int OFF_B4  = 37376;
constexpr int OFF_AL  = 37440;     // 16 f32 IRK alpha
constexpr int OFF_BE  = 37504;     // 4 f32 IRK beta
constexpr int OFF_SCR = 37568;     // 4 warps * 256 f32 (xs[32][4], Ks[32][4])
constexpr int OFF_STG = 41664;     // 4 warps * 4608 B (32 rows x 144B e4m3 staging)
constexpr int SMEM_TOTAL = OFF_STG + 4 * 4608;  // 60096
constexpr int ROWSTRIDE = 144;     // 36 words; 36 mod 32 = 4 -> bank = 4r+c, conflict-free
}

__device__ __align__(16) __nv_bfloat16 g_W1p[128 * 8];
__device__ __align__(16) unsigned long long g_W2f[2048];
__device__ __align__(16) unsigned long long g_W3f[2048];
__device__ __align__(16) unsigned long long g_W4f[128];

__device__ __forceinline__ unsigned char f2e4(float f) {
    return (unsigned char)__nv_cvt_float_to_fp8(f, __NV_SATFINITE, __NV_E4M3);
}

// Prepack weights.
// FP8 frag order for mma.m16n8k32 B (col-major n8k32): element (t, byte j) of
// u64 index (nt*4+kc)*32 + t:  low u32 byte j  = W[k = kc*32+(t%4)*4+j][n = nt*8+t/4]
//                              high u32 byte j = same with k += 16.
__global__ void pinns_prep(const float* __restrict__ W1, const float* __restrict__ W2,
                           const float* __restrict__ W3, const float* __restrict__ W4) {
    int i0 = blockIdx.x * blockDim.x + threadIdx.x;
    int stride = gridDim.x * blockDim.x;
    for (int idx = i0; idx < 2048; idx += stride) {
        int t = idx & 31, kcnt = idx >> 5;
        int kc = kcnt & 3, nt = kcnt >> 2;
        int n = nt * 8 + (t >> 2), kb = kc * 32 + (t & 3) * 4;
        unsigned long long v2 = 0, v3 = 0;
#pragma unroll
        for (int j = 0; j < 4; ++j) {
            v2 |= (unsigned long long)f2e4(W2[(kb + j) * 128 + n]) << (8 * j);
            v2 |= (unsigned long long)f2e4(W2[(kb + 16 + j) * 128 + n]) << (32 + 8 * j);
            v3 |= (unsigned long long)f2e4(W3[(kb + j) * 128 + n]) << (8 * j);
            v3 |= (unsigned long long)f2e4(W3[(kb + 16 + j) * 128 + n]) << (32 + 8 * j);
        }
        g_W2f[idx] = v2;
        g_W3f[idx] = v3;
    }
    for (int idx = i0; idx < 128; idx += stride) {
        int t = idx & 31, kc = idx >> 5;
        int n = t >> 2, kb = kc * 32 + (t & 3) * 4;
        unsigned long long v = 0;
        if (n < 4) {
#pragma unroll
            for (int j = 0; j < 4; ++j) {
                v |= (unsigned long long)f2e4(W4[(kb + j) * 4 + n]) << (8 * j);
                v |= (unsigned long long)f2e4(W4[(kb + 16 + j) * 4 + n]) << (32 + 8 * j);
            }
        }
        g_W4f[idx] = v;
    }
    for (int idx = i0; idx < 128 * 8; idx += stride) {
        int n = idx >> 3, k = idx & 7;
        g_W1p[idx] = __float2bfloat16((k < 4) ? W1[k * 128 + n] : 0.0f);
    }
}

// ---- helpers ----
__device__ __forceinline__ unsigned pack2(float lo, float hi) {
    unsigned d; asm("cvt.rn.bf16x2.f32 %0, %1, %2;" : "=r"(d) : "f"(hi), "f"(lo)); return d;
}
// tanh(lo,hi) -> e4m3x2 (byte0 = tanh(lo))
__device__ __forceinline__ unsigned short tanh_e4m3(float lo, float hi) {
    unsigned h;
    asm("cvt.rn.f16x2.f32 %0, %1, %2;" : "=r"(h) : "f"(hi), "f"(lo));
    asm("tanh.approx.f16x2 %0, %0;" : "+r"(h));
    unsigned short e;
    asm("cvt.rn.satfinite.e4m3x2.f16x2 %0, %1;" : "=h"(e) : "r"(h));
    return e;
}
__device__ __forceinline__ void lds32(unsigned& d, uint32_t a) {
    asm volatile("ld.shared.b32 %0, [%1];" : "=r"(d) : "r"(a));
}
__device__ __forceinline__ void lds64(unsigned& d0, unsigned& d1, uint32_t a) {
    asm volatile("ld.shared.v2.b32 {%0,%1}, [%2];" : "=r"(d0), "=r"(d1) : "r"(a));
}
__device__ __forceinline__ void sts16(uint32_t a, unsigned short v) {
    asm volatile("st.shared.b16 [%0], %1;" :: "r"(a), "h"(v));
}
__device__ __forceinline__ void ldsm_x4(unsigned& r0, unsigned& r1, unsigned& r2,
                                        unsigned& r3, uint32_t a) {
    asm volatile("ldmatrix.sync.aligned.m8n8.x4.shared.b16 {%0,%1,%2,%3}, [%4];"
                 : "=r"(r0), "=r"(r1), "=r"(r2), "=r"(r3) : "r"(a));
}
__device__ __forceinline__ void mma1688(float* c, unsigned a0, unsigned a1, unsigned b0) {
    asm volatile(
        "mma.sync.aligned.m16n8k8.row.col.f32.bf16.bf16.f32 "
        "{%0,%1,%2,%3}, {%4,%5}, {%6}, {%0,%1,%2,%3};"
        : "+f"(c[0]), "+f"(c[1]), "+f"(c[2]), "+f"(c[3])
        : "r"(a0), "r"(a1), "r"(b0));
}
__device__ __forceinline__ void mmaf8(float* c, const unsigned* a, unsigned b0, unsigned b1) {
    asm volatile(
        "mma.sync.aligned.m16n8k32.row.col.f32.e4m3.e4m3.f32 "
        "{%0,%1,%2,%3}, {%4,%5,%6,%7}, {%8,%9}, {%0,%1,%2,%3};"
        : "+f"(c[0]), "+f"(c[1]), "+f"(c[2]), "+f"(c[3])
        : "r"(a[0]), "r"(a[1]), "r"(a[2]), "r"(a[3]), "r"(b0), "r"(b1));
}

// Load A fragments (e4m3, 2 m16-tiles x 4 k-chunks of 32) from staging.
__device__ __forceinline__ void load_afrags(unsigned (&A0)[4][4], unsigned (&A1)[4][4],
                                            uint32_t stg, int g, int q) {
#pragma unroll
    for (int kc = 0; kc < 4; ++kc) {
        uint32_t a = stg + (uint32_t)(g * ROWSTRIDE + kc * 32 + q * 4);
        lds32(A0[kc][0], a);
        lds32(A0[kc][1], a + 8 * ROWSTRIDE);
        lds32(A0[kc][2], a + 16);
        lds32(A0[kc][3], a + 8 * ROWSTRIDE + 16);
        lds32(A1[kc][0], a + 16 * ROWSTRIDE);
        lds32(A1[kc][1], a + 24 * ROWSTRIDE);
        lds32(A1[kc][2], a + 16 * ROWSTRIDE + 16);
        lds32(A1[kc][3], a + 24 * ROWSTRIDE + 16);
    }
}

// 128->128 FP8 layer: read staging, MMA, tanh, write back to same staging.
__device__ __forceinline__ void layer_f8(uint32_t stg, uint32_t wb, const float* bias,
                                         int g, int q, int t) {
    unsigned A0[4][4], A1[4][4];
    load_afrags(A0, A1, stg, g, q);
    __syncwarp();
#pragma unroll
    for (int nt = 0; nt < 16; ++nt) {
        float bb0 = bias[8 * nt + 2 * q], bb1 = bias[8 * nt + 2 * q + 1];
        float c0[4] = {bb0, bb1, bb0, bb1};
        float c1[4] = {bb0, bb1, bb0, bb1};
#pragma unroll
        for (int kc = 0; kc < 4; ++kc) {
            unsigned b0, b1;
            lds64(b0, b1, wb + (uint32_t)(((nt * 4 + kc) * 32 + t) * 8));
            mmaf8(c0, A0[kc], b0, b1);
            mmaf8(c1, A1[kc], b0, b1);
        }
        uint32_t o = stg + (uint32_t)(8 * nt + 2 * q);
        sts16(o + g * ROWSTRIDE,        tanh_e4m3(c0[0], c0[1]));
        sts16(o + (g + 8) * ROWSTRIDE,  tanh_e4m3(c0[2], c0[3]));
        sts16(o + (g + 16) * ROWSTRIDE, tanh_e4m3(c1[0], c1[1]));
        sts16(o + (g + 24) * ROWSTRIDE, tanh_e4m3(c1[2], c1[3]));
    }
    __syncwarp();
}

__global__ void __launch_bounds__(128) pinns_main(
    const float* __restrict__ X0,
    const float* __restrict__ b1v, const float* __restrict__ b2v,
    const float* __restrict__ b3v, const float* __restrict__ b4v,
    const float* __restrict__ lam1, const float* __restrict__ lam2,
    const float* __restrict__ lam3, const float* __restrict__ lam4,
    const float* __restrict__ alphav, const float* __restrict__ betav,
    float* __restrict__ out) {
    extern __shared__ char smem[];
    const int tid = threadIdx.x;
    {
        int4* dw = (int4*)(smem + OFF_W2F);   // W2F + W3F contiguous: 2048 int4
        const int4* s2 = (const int4*)g_W2f;
        const int4* s3 = (const int4*)g_W3f;
        for (int i = tid; i < 1024; i += 128) {
            dw[i] = s2[i];
            dw[1024 + i] = s3[i];
        }
        if (tid < 64) ((int4*)(smem + OFF_W4F))[tid] = ((const int4*)g_W4f)[tid];
        if (tid < 128) {
            ((int4*)(smem + OFF_W1))[tid] = ((const int4*)g_W1p)[tid];
            ((float*)(smem + OFF_B1))[tid] = b1v[tid];
            ((float*)(smem + OFF_B2))[tid] = b2v[tid];
            ((float*)(smem + OFF_B3))[tid] = b3v[tid];
        }
        if (tid < 4) {
            ((float*)(smem + OFF_B4))[tid] = b4v[tid];
            ((float*)(smem + OFF_BE))[tid] = betav[tid];
        }
        if (tid < 16) ((float*)(smem + OFF_AL))[tid] = alphav[tid];
    }
    __syncthreads();

    const int w = tid >> 5, t = tid & 31;
    const int gw = blockIdx.x * 4 + w;      // rows [32*gw, 32*gw+32), batches [8gw,8gw+8)
    const int g = t >> 2, q = t & 3, myL = t & 7;

    float* xs = (float*)(smem + OFF_SCR) + w * 256;  // x stages [32][4]
    float* Ks = xs + 128;                             // K [32][4]
    const float* sB1 = (const float*)(smem + OFF_B1);
    const float* sB2 = (const float*)(smem + OFF_B2);
    const float* sB3 = (const float*)(smem + OFF_B3);
    const float* sB4 = (const float*)(smem + OFF_B4);
    const float* sAl = (const float*)(smem + OFF_AL);
    const float* sBe = (const float*)(smem + OFF_BE);

    const uint32_t uW1  = (uint32_t)__cvta_generic_to_shared(smem + OFF_W1);
    const uint32_t uW2f = (uint32_t)__cvta_generic_to_shared(smem + OFF_W2F);
    const uint32_t uW3f = (uint32_t)__cvta_generic_to_shared(smem + OFF_W3F);
    const uint32_t uW4f = (uint32_t)__cvta_generic_to_shared(smem + OFF_W4F);
    const uint32_t stg  = (uint32_t)__cvta_generic_to_shared(smem + OFF_STG) + w * 4608;

    const float aj0 = sAl[q], aj1 = sAl[4 + q], aj2 = sAl[8 + q], aj3 = sAl[12 + q];
    const float l1 = *lam1, l2 = *lam2, l3 = *lam3, l4 = *lam4;
    float x0r[4];
#pragma unroll
    for (int j = 0; j < 4; ++j) {
        x0r[j] = X0[(gw * 8 + (g >> 2) + 2 * j) * 4 + q];
        Ks[(g + 8 * j) * 4 + q] = 0.0f;
    }
    __syncwarp();

#pragma unroll 1
    for (int it = 0; it < 10; ++it) {
        // X stages: x[r][q] = X0 + dt * sum_i K[r][i]*alpha[i][q]
#pragma unroll
        for (int j = 0; j < 4; ++j) {
            const float* Ka = Ks + (g + 8 * j) * 4;
            xs[(g + 8 * j) * 4 + q] =
                x0r[j] + 0.1f * (Ka[0] * aj0 + Ka[1] * aj1 + Ka[2] * aj2 + Ka[3] * aj3);
        }
        __syncwarp();

        // A-frags for layer 1 (bf16 m16k8, k cols 4..7 zero), two m-tiles
        unsigned a00 = 0, a01 = 0, a10 = 0, a11 = 0;
        if (q < 2) {
            a00 = pack2(xs[g * 4 + 2 * q], xs[g * 4 + 2 * q + 1]);
            a01 = pack2(xs[(g + 8) * 4 + 2 * q], xs[(g + 8) * 4 + 2 * q + 1]);
            a10 = pack2(xs[(g + 16) * 4 + 2 * q], xs[(g + 16) * 4 + 2 * q + 1]);
            a11 = pack2(xs[(g + 24) * 4 + 2 * q], xs[(g + 24) * 4 + 2 * q + 1]);
        }

        // Layer-1 weight fragments (loop-carried reload keeps regs low)
        unsigned wv[16];
#pragma unroll
        for (int c = 0; c < 4; ++c)
            ldsm_x4(wv[4 * c], wv[4 * c + 1], wv[4 * c + 2], wv[4 * c + 3],
                    uW1 + (uint32_t)((c * 32 + (t >> 3) * 8 + myL) * 16));

        // Layer 1: 4(->8) -> 128 bf16; outputs tanh'd to e4m3 staging
#pragma unroll
        for (int jp = 0; jp < 8; ++jp) {
            float be0 = sB1[16 * jp + 2 * q], be1 = sB1[16 * jp + 2 * q + 1];
            float bo0 = sB1[16 * jp + 8 + 2 * q], bo1 = sB1[16 * jp + 8 + 2 * q + 1];
            float cE0[4] = {be0, be1, be0, be1};
            float cO0[4] = {bo0, bo1, bo0, bo1};
            float cE1[4] = {be0, be1, be0, be1};
            float cO1[4] = {bo0, bo1, bo0, bo1};
            mma1688(cE0, a00, a01, wv[2 * jp]);
            mma1688(cO0, a00, a01, wv[2 * jp + 1]);
            mma1688(cE1, a10, a11, wv[2 * jp]);
            mma1688(cO1, a10, a11, wv[2 * jp + 1]);
            uint32_t o = stg + (uint32_t)(16 * jp + 2 * q);
            sts16(o + g * ROWSTRIDE,            tanh_e4m3(cE0[0], cE0[1]));
            sts16(o + (g + 8) * ROWSTRIDE,      tanh_e4m3(cE0[2], cE0[3]));
            sts16(o + g * ROWSTRIDE + 8,        tanh_e4m3(cO0[0], cO0[1]));
            sts16(o + (g + 8) * ROWSTRIDE + 8,  tanh_e4m3(cO0[2], cO0[3]));
            sts16(o + (g + 16) * ROWSTRIDE,     tanh_e4m3(cE1[0], cE1[1]));
            sts16(o + (g + 24) * ROWSTRIDE,     tanh_e4m3(cE1[2], cE1[3]));
            sts16(o + (g + 16) * ROWSTRIDE + 8, tanh_e4m3(cO1[0], cO1[1]));
            sts16(o + (g + 24) * ROWSTRIDE + 8, tanh_e4m3(cO1[2], cO1[3]));
        }
        __syncwarp();

        layer_f8(stg, uW2f, sB2, g, q, t);  // layer 2 (FP8)
        layer_f8(stg, uW3f, sB3, g, q, t);  // layer 3 (FP8)

        // Layer 4: 128 -> 4 (n padded to 8), FP8, no tanh
        float c40[4], c41[4];
        {
            unsigned A0[4][4], A1[4][4];
            load_afrags(A0, A1, stg, g, q);
            float bb0 = (q < 2) ? sB4[2 * q] : 0.0f;
            float bb1 = (q < 2) ? sB4[2 * q + 1] : 0.0f;
            c40[0] = bb0; c40[1] = bb1; c40[2] = bb0; c40[3] = bb1;
            c41[0] = bb0; c41[1] = bb1; c41[2] = bb0; c41[3] = bb1;
#pragma unroll
            for (int kc = 0; kc < 4; ++kc) {
                unsigned b0, b1;
                lds64(b0, b1, uW4f + (uint32_t)((kc * 32 + t) * 8));
                mmaf8(c40, A0[kc], b0, b1);
                mmaf8(c41, A1[kc], b0, b1);
            }
        }
        // Hamiltonian vf: swap H col pairs {0,1}<->{2,3} across lanes q=0<->1
        float o0 = __shfl_xor_sync(0xffffffffu, c40[0], 1);
        float o1 = __shfl_xor_sync(0xffffffffu, c40[1], 1);
        float o2 = __shfl_xor_sync(0xffffffffu, c40[2], 1);
        float o3 = __shfl_xor_sync(0xffffffffu, c40[3], 1);
        float p0 = __shfl_xor_sync(0xffffffffu, c41[0], 1);
        float p1 = __shfl_xor_sync(0xffffffffu, c41[1], 1);
        float p2 = __shfl_xor_sync(0xffffffffu, c41[2], 1);
        float p3 = __shfl_xor_sync(0xffffffffu, c41[3], 1);
        if (q == 0) {  // K[0],K[1] = -l1*H[2,3] - l2*x[2,3]
            Ks[g * 4 + 0] = -l1 * o0 - l2 * xs[g * 4 + 2];
            Ks[g * 4 + 1] = -l1 * o1 - l2 * xs[g * 4 + 3];
            Ks[(g + 8) * 4 + 0] = -l1 * o2 - l2 * xs[(g + 8) * 4 + 2];
            Ks[(g + 8) * 4 + 1] = -l1 * o3 - l2 * xs[(g + 8) * 4 + 3];
            Ks[(g + 16) * 4 + 0] = -l1 * p0 - l2 * xs[(g + 16) * 4 + 2];
            Ks[(g + 16) * 4 + 1] = -l1 * p1 - l2 * xs[(g + 16) * 4 + 3];
            Ks[(g + 24) * 4 + 0] = -l1 * p2 - l2 * xs[(g + 24) * 4 + 2];
            Ks[(g + 24) * 4 + 1] = -l1 * p3 - l2 * xs[(g + 24) * 4 + 3];
        } else if (q == 1) {  // K[2],K[3] = l3*H[0,1] + l4*x[0,1]
            Ks[g * 4 + 2] = l3 * o0 + l4 * xs[g * 4 + 0];
            Ks[g * 4 + 3] = l3 * o1 + l4 * xs[g * 4 + 1];
            Ks[(g + 8) * 4 + 2] = l3 * o2 + l4 * xs[(g + 8) * 4 + 0];
            Ks[(g + 8) * 4 + 3] = l3 * o3 + l4 * xs[(g + 8) * 4 + 1];
            Ks[(g + 16) * 4 + 2] = l3 * p0 + l4 * xs[(g + 16) * 4 + 0];
            Ks[(g + 16) * 4 + 3] = l3 * p1 + l4 * xs[(g + 16) * 4 + 1];
            Ks[(g + 24) * 4 + 2] = l3 * p2 + l4 * xs[(g + 24) * 4 + 0];
            Ks[(g + 24) * 4 + 3] = l3 * p3 + l4 * xs[(g + 24) * 4 + 1];
        }
        __syncwarp();
    }

    // Final combine: X1 = X0 + dt * sum_s beta[s]*K[b][s][:]; 8 batches/warp
    {
        int bb = t >> 2, c = t & 3;
        float s = sBe[0] * Ks[(bb * 4 + 0) * 4 + c] + sBe[1] * Ks[(bb * 4 + 1) * 4 + c] +
                  sBe[2] * Ks[(bb * 4 + 2) * 4 + c] + sBe[3] * Ks[(bb * 4 + 3) * 4 + c];
        int gi = (gw * 8 + bb) * 4 + c;
        out[gi] = X0[gi] + 0.1f * s;
    }
}

extern "C" void kernel_launch(void* const* d_in, const int* in_sizes, int n_in,
                              void* d_out, int out_size) {
    const float* X0    = (const float*)d_in[0];
    const float* W1    = (const float*)d_in[1];
    const float* b1    = (const float*)d_in[2];
    const float* W2    = (const float*)d_in[3];
    const float* b2    = (const float*)d_in[4];
    const float* W3    = (const float*)d_in[5];
    const float* b3    = (const float*)d_in[6];
    const float* W4    = (const float*)d_in[7];
    const float* b4    = (const float*)d_in[8];
    const float* lam1  = (const float*)d_in[9];
    const float* lam2  = (const float*)d_in[10];
    const float* lam3  = (const float*)d_in[11];
    const float* lam4  = (const float*)d_in[12];
    const float* alpha = (const float*)d_in[13];
    const float* beta  = (const float*)d_in[14];

    cudaFuncSetAttribute(pinns_main, cudaFuncAttributeMaxDynamicSharedMemorySize, SMEM_TOTAL);
    pinns_prep<<<64, 256>>>(W1, W2, W3, W4);
    pinns_main<<<2048, 128, SMEM_TOTAL>>>(X0, b1, b2, b3, b4,
                                          lam1, lam2, lam3, lam4,
                                          alpha, beta, (float*)d_out);
}

// round 9
// speedup vs baseline: 1.6039x; 1.6039x over previous
#include <cuda_runtime.h>
#include <cuda_bf16.h>
#include <stdint.h>

// PINNS IRK fixed-point: 262144 independent rows, 10 iters of 4->128->128->128->4
// tanh MLP. Warp-level bf16 mma.sync, register-resident activations, M=32/warp.
// R9: force 3 blocks/SM (__launch_bounds__(128,3) -> 170-reg cap) to lift
// occupancy 2->3 warps/SMSP and close the latency gap (tensor 72.5% -> ~88%).
// wv (layer-1 weight frags) reloaded per-iter to shorten live ranges.

namespace {
constexpr int OFF_W2  = 0;        // 128x128 bf16 [n][k], swizzled
constexpr int OFF_W3  = 32768;
constexpr int OFF_W1  = 65536;    // 128x8 bf16 [n][k pad 4->8]
constexpr int OFF_W4  = 67584;    // 8x128 bf16 [n pad 4->8][k], swizzled
constexpr int OFF_B1  = 69632;
constexpr int OFF_B2  = 70144;
constexpr int OFF_B3  = 70656;
constexpr int OFF_B4  = 71168;
constexpr int OFF_AL  = 71232;    // 16 f32 IRK alpha
constexpr int OFF_BE  = 71296;    // 4 f32 IRK beta
constexpr int OFF_SCR = 71360;    // 4 warps * 256 f32 (xs[32][4], Ks[32][4])
constexpr int SMEM_TOTAL = OFF_SCR + 4 * 256 * 4;  // 75456; x3 blocks = 226368 <= 228KB
}

__device__ __align__(16) __nv_bfloat16 g_W1p[128 * 8];
__device__ __align__(16) __nv_bfloat16 g_W2s[128 * 128];
__device__ __align__(16) __nv_bfloat16 g_W3s[128 * 128];
__device__ __align__(16) __nv_bfloat16 g_W4p[8 * 128];

// Transpose W[k][n] -> Wt[n][k] bf16; XOR-swizzle 16B chunks: halfword offset
// n*128 + (((k>>3) ^ (n&7))<<3) + (k&7)
__global__ void pinns_prep(const float* __restrict__ W1, const float* __restrict__ W2,
                           const float* __restrict__ W3, const float* __restrict__ W4) {
    int i0 = blockIdx.x * blockDim.x + threadIdx.x;
    int stride = gridDim.x * blockDim.x;
    for (int idx = i0; idx < 128 * 128; idx += stride) {
        int n = idx >> 7, k = idx & 127;
        int off = (n << 7) + ((((k >> 3) ^ (n & 7)) << 3) | (k & 7));
        g_W2s[off] = __float2bfloat16(W2[k * 128 + n]);
        g_W3s[off] = __float2bfloat16(W3[k * 128 + n]);
    }
    for (int idx = i0; idx < 128 * 8; idx += stride) {
        int n = idx >> 3, k = idx & 7;
        g_W1p[idx] = __float2bfloat16((k < 4) ? W1[k * 128 + n] : 0.0f);
    }
    for (int idx = i0; idx < 8 * 128; idx += stride) {
        int n = idx >> 7, k = idx & 127;
        int off = (n << 7) + ((((k >> 3) ^ (n & 7)) << 3) | (k & 7));
        g_W4p[off] = __float2bfloat16((n < 4) ? W4[k * 4 + n] : 0.0f);
    }
}

__device__ __forceinline__ float tanh_ap(float x) {
    float y; asm("tanh.approx.f32 %0, %1;" : "=f"(y) : "f"(x)); return y;
}
__device__ __forceinline__ unsigned pack2(float lo, float hi) {
    unsigned d; asm("cvt.rn.bf16x2.f32 %0, %1, %2;" : "=r"(d) : "f"(hi), "f"(lo)); return d;
}
__device__ __forceinline__ unsigned tp(float a, float b) {
    return pack2(tanh_ap(a), tanh_ap(b));
}
__device__ __forceinline__ void ldsm_x2(unsigned& r0, unsigned& r1, uint32_t a) {
    asm volatile("ldmatrix.sync.aligned.m8n8.x2.shared.b16 {%0,%1}, [%2];"
                 : "=r"(r0), "=r"(r1) : "r"(a));
}
__device__ __forceinline__ void ldsm_x4(unsigned& r0, unsigned& r1, unsigned& r2,
                                        unsigned& r3, uint32_t a) {
    asm volatile("ldmatrix.sync.aligned.m8n8.x4.shared.b16 {%0,%1,%2,%3}, [%4];"
                 : "=r"(r0), "=r"(r1), "=r"(r2), "=r"(r3) : "r"(a));
}
__device__ __forceinline__ void mma16816(float* c, const unsigned* a, unsigned b0, unsigned b1) {
    asm volatile(
        "mma.sync.aligned.m16n8k16.row.col.f32.bf16.bf16.f32 "
        "{%0,%1,%2,%3}, {%4,%5,%6,%7}, {%8,%9}, {%0,%1,%2,%3};"
        : "+f"(c[0]), "+f"(c[1]), "+f"(c[2]), "+f"(c[3])
        : "r"(a[0]), "r"(a[1]), "r"(a[2]), "r"(a[3]), "r"(b0), "r"(b1));
}
__device__ __forceinline__ void mma1688(float* c, unsigned a0, unsigned a1, unsigned b0) {
    asm volatile(
        "mma.sync.aligned.m16n8k8.row.col.f32.bf16.bf16.f32 "
        "{%0,%1,%2,%3}, {%4,%5}, {%6}, {%0,%1,%2,%3};"
        : "+f"(c[0]), "+f"(c[1]), "+f"(c[2]), "+f"(c[3])
        : "r"(a0), "r"(a1), "r"(b0));
}

// 128->128 layer for two m16 tiles sharing each B fragment (4 MMAs per ldsm_x4).
__device__ __forceinline__ void layer128m32(
    const unsigned (&a0)[8][4], const unsigned (&a1)[8][4],
    unsigned (&o0)[8][4], unsigned (&o1)[8][4],
    uint32_t laneBase, const float* bias, int q, int myL, int hb) {
#pragma unroll
    for (int jp = 0; jp < 8; ++jp) {
        float be0 = bias[16 * jp + 2 * q], be1 = bias[16 * jp + 2 * q + 1];
        float bo0 = bias[16 * jp + 8 + 2 * q], bo1 = bias[16 * jp + 8 + 2 * q + 1];
        float cE0[4] = {be0, be1, be0, be1};
        float cO0[4] = {bo0, bo1, bo0, bo1};
        float cE1[4] = {be0, be1, be0, be1};
        float cO1[4] = {bo0, bo1, bo0, bo1};
#pragma unroll
        for (int kc = 0; kc < 8; ++kc) {
            unsigned b0, b1, b2, b3;
            uint32_t ad = laneBase + jp * 4096 + ((((kc << 1) | hb) ^ myL) << 4);
            ldsm_x4(b0, b1, b2, b3, ad);
            mma16816(cE0, a0[kc], b0, b1);
            mma16816(cO0, a0[kc], b2, b3);
            mma16816(cE1, a1[kc], b0, b1);
            mma16816(cO1, a1[kc], b2, b3);
        }
        o0[jp][0] = tp(cE0[0], cE0[1]);
        o0[jp][1] = tp(cE0[2], cE0[3]);
        o0[jp][2] = tp(cO0[0], cO0[1]);
        o0[jp][3] = tp(cO0[2], cO0[3]);
        o1[jp][0] = tp(cE1[0], cE1[1]);
        o1[jp][1] = tp(cE1[2], cE1[3]);
        o1[jp][2] = tp(cO1[0], cO1[1]);
        o1[jp][3] = tp(cO1[2], cO1[3]);
    }
}

__global__ void __launch_bounds__(128, 3) pinns_main(
    const float* __restrict__ X0,
    const float* __restrict__ b1v, const float* __restrict__ b2v,
    const float* __restrict__ b3v, const float* __restrict__ b4v,
    const float* __restrict__ lam1, const float* __restrict__ lam2,
    const float* __restrict__ lam3, const float* __restrict__ lam4,
    const float* __restrict__ alphav, const float* __restrict__ betav,
    float* __restrict__ out) {
    extern __shared__ char smem[];
    const int tid = threadIdx.x;
    {
        const int4* s2 = (const int4*)g_W2s;
        const int4* s3 = (const int4*)g_W3s;
        int4* d2 = (int4*)(smem + OFF_W2);
        int4* d3 = (int4*)(smem + OFF_W3);
        for (int i = tid; i < 2048; i += 128) { d2[i] = s2[i]; d3[i] = s3[i]; }
        if (tid < 128) {
            ((int4*)(smem + OFF_W1))[tid] = ((const int4*)g_W1p)[tid];
            ((int4*)(smem + OFF_W4))[tid] = ((const int4*)g_W4p)[tid];
            ((float*)(smem + OFF_B1))[tid] = b1v[tid];
            ((float*)(smem + OFF_B2))[tid] = b2v[tid];
            ((float*)(smem + OFF_B3))[tid] = b3v[tid];
        }
        if (tid < 4) {
            ((float*)(smem + OFF_B4))[tid] = b4v[tid];
            ((float*)(smem + OFF_BE))[tid] = betav[tid];
        }
        if (tid < 16) ((float*)(smem + OFF_AL))[tid] = alphav[tid];
    }
    __syncthreads();

    const int w = tid >> 5, t = tid & 31;
    const int gw = blockIdx.x * 4 + w;      // rows [32*gw, 32*gw+32), batches [8gw,8gw+8)
    const int g = t >> 2, q = t & 3, myL = t & 7, hb = (t >> 3) & 1;

    float* xs = (float*)(smem + OFF_SCR) + w * 256;  // x stages [32][4]
    float* Ks = xs + 128;                             // K [32][4]
    const float* sB1 = (const float*)(smem + OFF_B1);
    const float* sB2 = (const float*)(smem + OFF_B2);
    const float* sB3 = (const float*)(smem + OFF_B3);
    const float* sB4 = (const float*)(smem + OFF_B4);
    const float* sAl = (const float*)(smem + OFF_AL);
    const float* sBe = (const float*)(smem + OFF_BE);

    const uint32_t uW1 = (uint32_t)__cvta_generic_to_shared(smem + OFF_W1);
    const uint32_t nOff = (uint32_t)(myL * 256 + (t >> 4) * 2048);
    const uint32_t base2 = (uint32_t)__cvta_generic_to_shared(smem + OFF_W2) + nOff;
    const uint32_t base3 = (uint32_t)__cvta_generic_to_shared(smem + OFF_W3) + nOff;
    const uint32_t base4 = (uint32_t)__cvta_generic_to_shared(smem + OFF_W4) + myL * 256;

    const float aj0 = sAl[q], aj1 = sAl[4 + q], aj2 = sAl[8 + q], aj3 = sAl[12 + q];
    const float l1 = *lam1, l2 = *lam2, l3 = *lam3, l4 = *lam4;
    // lane handles rows r = g + 8j (j=0..3); batch = 8gw + (g>>2) + 2j
    float x0r[4];
#pragma unroll
    for (int j = 0; j < 4; ++j) {
        x0r[j] = X0[(gw * 8 + (g >> 2) + 2 * j) * 4 + q];
        Ks[(g + 8 * j) * 4 + q] = 0.0f;
    }
    __syncwarp();

    unsigned fA0[8][4], fA1[8][4], fB0[8][4], fB1[8][4];

#pragma unroll 1
    for (int it = 0; it < 10; ++it) {
        // X stages: x[r][q] = X0 + dt * sum_i K[r][i]*alpha[i][q]
#pragma unroll
        for (int j = 0; j < 4; ++j) {
            const float* Ka = Ks + (g + 8 * j) * 4;
            xs[(g + 8 * j) * 4 + q] =
                x0r[j] + 0.1f * (Ka[0] * aj0 + Ka[1] * aj1 + Ka[2] * aj2 + Ka[3] * aj3);
        }
        __syncwarp();

        // A-frags for layer 1 (m16 x k8, k cols 4..7 zero), two m-tiles
        unsigned a00 = 0, a01 = 0, a10 = 0, a11 = 0;
        if (q < 2) {
            a00 = pack2(xs[g * 4 + 2 * q], xs[g * 4 + 2 * q + 1]);
            a01 = pack2(xs[(g + 8) * 4 + 2 * q], xs[(g + 8) * 4 + 2 * q + 1]);
            a10 = pack2(xs[(g + 16) * 4 + 2 * q], xs[(g + 16) * 4 + 2 * q + 1]);
            a11 = pack2(xs[(g + 24) * 4 + 2 * q], xs[(g + 24) * 4 + 2 * q + 1]);
        }

        // Layer-1 weight fragments (reloaded per-iter: short live range under reg cap)
        unsigned wv[16];
#pragma unroll
        for (int c = 0; c < 4; ++c)
            ldsm_x4(wv[4 * c], wv[4 * c + 1], wv[4 * c + 2], wv[4 * c + 3],
                    uW1 + (uint32_t)((c * 32 + (t >> 3) * 8 + myL) * 16));

        // Layer 1: 4(->8) -> 128, both m-tiles
#pragma unroll
        for (int jp = 0; jp < 8; ++jp) {
            float be0 = sB1[16 * jp + 2 * q], be1 = sB1[16 * jp + 2 * q + 1];
            float bo0 = sB1[16 * jp + 8 + 2 * q], bo1 = sB1[16 * jp + 8 + 2 * q + 1];
            float cE0[4] = {be0, be1, be0, be1};
            float cO0[4] = {bo0, bo1, bo0, bo1};
            float cE1[4] = {be0, be1, be0, be1};
            float cO1[4] = {bo0, bo1, bo0, bo1};
            mma1688(cE0, a00, a01, wv[2 * jp]);
            mma1688(cO0, a00, a01, wv[2 * jp + 1]);
            mma1688(cE1, a10, a11, wv[2 * jp]);
            mma1688(cO1, a10, a11, wv[2 * jp + 1]);
            fA0[jp][0] = tp(cE0[0], cE0[1]);
            fA0[jp][1] = tp(cE0[2], cE0[3]);
            fA0[jp][2] = tp(cO0[0], cO0[1]);
            fA0[jp][3] = tp(cO0[2], cO0[3]);
            fA1[jp][0] = tp(cE1[0], cE1[1]);
            fA1[jp][1] = tp(cE1[2], cE1[3]);
            fA1[jp][2] = tp(cO1[0], cO1[1]);
            fA1[jp][3] = tp(cO1[2], cO1[3]);
        }

        layer128m32(fA0, fA1, fB0, fB1, base2, sB2, q, myL, hb);  // layer 2
        layer128m32(fB0, fB1, fA0, fA1, base3, sB3, q, myL, hb);  // layer 3

        // Layer 4: 128 -> 4 (n padded to 8), no tanh, both m-tiles share B
        float c40[4], c41[4];
        {
            float bb0 = (q < 2) ? sB4[2 * q] : 0.0f;
            float bb1 = (q < 2) ? sB4[2 * q + 1] : 0.0f;
            c40[0] = bb0; c40[1] = bb1; c40[2] = bb0; c40[3] = bb1;
            c41[0] = bb0; c41[1] = bb1; c41[2] = bb0; c41[3] = bb1;
#pragma unroll
            for (int kc = 0; kc < 8; ++kc) {
                unsigned b0, b1;
                uint32_t sw = (uint32_t)(((((kc << 1) | hb)) ^ myL) << 4);
                ldsm_x2(b0, b1, base4 + sw);
                mma16816(c40, fA0[kc], b0, b1);
                mma16816(c41, fA1[kc], b0, b1);
            }
        }
        // Hamiltonian vf: swap H col pairs {0,1}<->{2,3} across lanes q=0<->1
        float o0 = __shfl_xor_sync(0xffffffffu, c40[0], 1);
        float o1 = __shfl_xor_sync(0xffffffffu, c40[1], 1);
        float o2 = __shfl_xor_sync(0xffffffffu, c40[2], 1);
        float o3 = __shfl_xor_sync(0xffffffffu, c40[3], 1);
        float p0 = __shfl_xor_sync(0xffffffffu, c41[0], 1);
        float p1 = __shfl_xor_sync(0xffffffffu, c41[1], 1);
        float p2 = __shfl_xor_sync(0xffffffffu, c41[2], 1);
        float p3 = __shfl_xor_sync(0xffffffffu, c41[3], 1);
        if (q == 0) {  // K[0],K[1] = -l1*H[2,3] - l2*x[2,3]
            Ks[g * 4 + 0] = -l1 * o0 - l2 * xs[g * 4 + 2];
            Ks[g * 4 + 1] = -l1 * o1 - l2 * xs[g * 4 + 3];
            Ks[(g + 8) * 4 + 0] = -l1 * o2 - l2 * xs[(g + 8) * 4 + 2];
            Ks[(g + 8) * 4 + 1] = -l1 * o3 - l2 * xs[(g + 8) * 4 + 3];
            Ks[(g + 16) * 4 + 0] = -l1 * p0 - l2 * xs[(g + 16) * 4 + 2];
            Ks[(g + 16) * 4 + 1] = -l1 * p1 - l2 * xs[(g + 16) * 4 + 3];
            Ks[(g + 24) * 4 + 0] = -l1 * p2 - l2 * xs[(g + 24) * 4 + 2];
            Ks[(g + 24) * 4 + 1] = -l1 * p3 - l2 * xs[(g + 24) * 4 + 3];
        } else if (q == 1) {  // K[2],K[3] = l3*H[0,1] + l4*x[0,1]
            Ks[g * 4 + 2] = l3 * o0 + l4 * xs[g * 4 + 0];
            Ks[g * 4 + 3] = l3 * o1 + l4 * xs[g * 4 + 1];
            Ks[(g + 8) * 4 + 2] = l3 * o2 + l4 * xs[(g + 8) * 4 + 0];
            Ks[(g + 8) * 4 + 3] = l3 * o3 + l4 * xs[(g + 8) * 4 + 1];
            Ks[(g + 16) * 4 + 2] = l3 * p0 + l4 * xs[(g + 16) * 4 + 0];
            Ks[(g + 16) * 4 + 3] = l3 * p1 + l4 * xs[(g + 16) * 4 + 1];
            Ks[(g + 24) * 4 + 2] = l3 * p2 + l4 * xs[(g + 24) * 4 + 0];
            Ks[(g + 24) * 4 + 3] = l3 * p3 + l4 * xs[(g + 24) * 4 + 1];
        }
        __syncwarp();
    }

    // Final combine: X1 = X0 + dt * sum_s beta[s]*K[b][s][:]; 8 batches/warp
    {
        int bb = t >> 2, c = t & 3;
        float s = sBe[0] * Ks[(bb * 4 + 0) * 4 + c] + sBe[1] * Ks[(bb * 4 + 1) * 4 + c] +
                  sBe[2] * Ks[(bb * 4 + 2) * 4 + c] + sBe[3] * Ks[(bb * 4 + 3) * 4 + c];
        int gi = (gw * 8 + bb) * 4 + c;
        out[gi] = X0[gi] + 0.1f * s;
    }
}

extern "C" void kernel_launch(void* const* d_in, const int* in_sizes, int n_in,
                              void* d_out, int out_size) {
    const float* X0    = (const float*)d_in[0];
    const float* W1    = (const float*)d_in[1];
    const float* b1    = (const float*)d_in[2];
    const float* W2    = (const float*)d_in[3];
    const float* b2    = (const float*)d_in[4];
    const float* W3    = (const float*)d_in[5];
    const float* b3    = (const float*)d_in[6];
    const float* W4    = (const float*)d_in[7];
    const float* b4    = (const float*)d_in[8];
    const float* lam1  = (const float*)d_in[9];
    const float* lam2  = (const float*)d_in[10];
    const float* lam3  = (const float*)d_in[11];
    const float* lam4  = (const float*)d_in[12];
    const float* alpha = (const float*)d_in[13];
    const float* beta  = (const float*)d_in[14];

    cudaFuncSetAttribute(pinns_main, cudaFuncAttributeMaxDynamicSharedMemorySize, SMEM_TOTAL);
    pinns_prep<<<64, 256>>>(W1, W2, W3, W4);
    pinns_main<<<2048, 128, SMEM_TOTAL>>>(X0, b1, b2, b3, b4,
                                          lam1, lam2, lam3, lam4,
                                          alpha, beta, (float*)d_out);
}

// round 10
// speedup vs baseline: 1.6847x; 1.0504x over previous
#include <cuda_runtime.h>
#include <cuda_fp16.h>
#include <stdint.h>

// PINNS IRK fixed-point: 262144 independent rows, 10 iters of 4->128->128->128->4
// tanh MLP. R10: fp16 weights/activations with **f16 accumulators**
// (mma.sync.m16n8k16.f16 = 2-reg C operand; testing the operand-bandwidth model
// of sm_103a mma.sync throughput). D-fragment (f16x2) IS the next layer's
// A-fragment -> epilogue is a single tanh.approx.f16x2 per reg, zero cvt/pack.
// M=32 rows/warp, block = 4 warps, grid = 2048, 3 blocks/SM.

namespace {
constexpr int OFF_W2  = 0;        // 128x128 f16 [n][k], swizzled
constexpr int OFF_W3  = 32768;
constexpr int OFF_W1  = 65536;    // 128x8 f16 [n][k pad 4->8]
constexpr int OFF_W4  = 67584;    // 8x128 f16 [n pad 4->8][k], swizzled
constexpr int OFF_B1  = 69632;
constexpr int OFF_B2  = 70144;
constexpr int OFF_B3  = 70656;
constexpr int OFF_B4  = 71168;
constexpr int OFF_AL  = 71232;    // 16 f32 IRK alpha
constexpr int OFF_BE  = 71296;    // 4 f32 IRK beta
constexpr int OFF_SCR = 71360;    // 4 warps * 256 f32 (xs[32][4], Ks[32][4])
constexpr int SMEM_TOTAL = OFF_SCR + 4 * 256 * 4;  // 75456; x3 = 226368 <= 228KB
}

__device__ __align__(16) __half g_W1p[128 * 8];
__device__ __align__(16) __half g_W2s[128 * 128];
__device__ __align__(16) __half g_W3s[128 * 128];
__device__ __align__(16) __half g_W4p[8 * 128];

// Transpose W[k][n] -> Wt[n][k] f16; XOR-swizzle 16B chunks: halfword offset
// n*128 + (((k>>3) ^ (n&7))<<3) + (k&7)
__global__ void pinns_prep(const float* __restrict__ W1, const float* __restrict__ W2,
                           const float* __restrict__ W3, const float* __restrict__ W4) {
    int i0 = blockIdx.x * blockDim.x + threadIdx.x;
    int stride = gridDim.x * blockDim.x;
    for (int idx = i0; idx < 128 * 128; idx += stride) {
        int n = idx >> 7, k = idx & 127;
        int off = (n << 7) + ((((k >> 3) ^ (n & 7)) << 3) | (k & 7));
        g_W2s[off] = __float2half(W2[k * 128 + n]);
        g_W3s[off] = __float2half(W3[k * 128 + n]);
    }
    for (int idx = i0; idx < 128 * 8; idx += stride) {
        int n = idx >> 3, k = idx & 7;
        g_W1p[idx] = __float2half((k < 4) ? W1[k * 128 + n] : 0.0f);
    }
    for (int idx = i0; idx < 8 * 128; idx += stride) {
        int n = idx >> 7, k = idx & 127;
        int off = (n << 7) + ((((k >> 3) ^ (n & 7)) << 3) | (k & 7));
        g_W4p[off] = __float2half((n < 4) ? W4[k * 4 + n] : 0.0f);
    }
}

// pack f32 pair to f16x2: low half <- lo, high half <- hi
__device__ __forceinline__ unsigned packh(float lo, float hi) {
    unsigned d; asm("cvt.rn.f16x2.f32 %0, %1, %2;" : "=r"(d) : "f"(hi), "f"(lo)); return d;
}
__device__ __forceinline__ unsigned tanh2(unsigned v) {
    unsigned r; asm("tanh.approx.f16x2 %0, %1;" : "=r"(r) : "r"(v)); return r;
}
__device__ __forceinline__ void unpackh(float& lo, float& hi, unsigned v) {
    asm("{.reg .f16 l, h;\n\t mov.b32 {l, h}, %2;\n\t"
        "cvt.f32.f16 %0, l;\n\t cvt.f32.f16 %1, h;}"
        : "=f"(lo), "=f"(hi) : "r"(v));
}
__device__ __forceinline__ void ldsm_x2(unsigned& r0, unsigned& r1, uint32_t a) {
    asm volatile("ldmatrix.sync.aligned.m8n8.x2.shared.b16 {%0,%1}, [%2];"
                 : "=r"(r0), "=r"(r1) : "r"(a));
}
__device__ __forceinline__ void ldsm_x4(unsigned& r0, unsigned& r1, unsigned& r2,
                                        unsigned& r3, uint32_t a) {
    asm volatile("ldmatrix.sync.aligned.m8n8.x4.shared.b16 {%0,%1,%2,%3}, [%4];"
                 : "=r"(r0), "=r"(r1), "=r"(r2), "=r"(r3) : "r"(a));
}
// m16n8k16, f16 accumulate in-place (2-reg C/D)
__device__ __forceinline__ void mmah(unsigned* c, const unsigned* a, unsigned b0, unsigned b1) {
    asm volatile(
        "mma.sync.aligned.m16n8k16.row.col.f16.f16.f16.f16 "
        "{%0,%1}, {%2,%3,%4,%5}, {%6,%7}, {%0,%1};"
        : "+r"(c[0]), "+r"(c[1])
        : "r"(a[0]), "r"(a[1]), "r"(a[2]), "r"(a[3]), "r"(b0), "r"(b1));
}
// m16n8k8, f16 accumulate in-place
__device__ __forceinline__ void mmah8(unsigned* c, unsigned a0, unsigned a1, unsigned b0) {
    asm volatile(
        "mma.sync.aligned.m16n8k8.row.col.f16.f16.f16.f16 "
        "{%0,%1}, {%2,%3}, {%4}, {%0,%1};"
        : "+r"(c[0]), "+r"(c[1])
        : "r"(a0), "r"(a1), "r"(b0));
}

// 128->128 layer, two m16 tiles sharing each ldsm_x4 B fragment, f16 accum.
// Output regs map 1:1 onto next layer's A-fragments after tanh.
__device__ __forceinline__ void layer128m32(
    const unsigned (&a0)[8][4], const unsigned (&a1)[8][4],
    unsigned (&o0)[8][4], unsigned (&o1)[8][4],
    uint32_t laneBase, const float* bias, int q, int myL, int hb) {
#pragma unroll
    for (int jp = 0; jp < 8; ++jp) {
        unsigned bE = packh(bias[16 * jp + 2 * q], bias[16 * jp + 2 * q + 1]);
        unsigned bO = packh(bias[16 * jp + 8 + 2 * q], bias[16 * jp + 8 + 2 * q + 1]);
        unsigned cE0[2] = {bE, bE};   // rows g, g+8
        unsigned cO0[2] = {bO, bO};
        unsigned cE1[2] = {bE, bE};   // rows g+16, g+24
        unsigned cO1[2] = {bO, bO};
#pragma unroll
        for (int kc = 0; kc < 8; ++kc) {
            unsigned b0, b1, b2, b3;
            uint32_t ad = laneBase + jp * 4096 + ((((kc << 1) | hb) ^ myL) << 4);
            ldsm_x4(b0, b1, b2, b3, ad);
            mmah(cE0, a0[kc], b0, b1);
            mmah(cO0, a0[kc], b2, b3);
            mmah(cE1, a1[kc], b0, b1);
            mmah(cO1, a1[kc], b2, b3);
        }
        o0[jp][0] = tanh2(cE0[0]);
        o0[jp][1] = tanh2(cE0[1]);
        o0[jp][2] = tanh2(cO0[0]);
        o0[jp][3] = tanh2(cO0[1]);
        o1[jp][0] = tanh2(cE1[0]);
        o1[jp][1] = tanh2(cE1[1]);
        o1[jp][2] = tanh2(cO1[0]);
        o1[jp][3] = tanh2(cO1[1]);
    }
}

__global__ void __launch_bounds__(128, 3) pinns_main(
    const float* __restrict__ X0,
    const float* __restrict__ b1v, const float* __restrict__ b2v,
    const float* __restrict__ b3v, const float* __restrict__ b4v,
    const float* __restrict__ lam1, const float* __restrict__ lam2,
    const float* __restrict__ lam3, const float* __restrict__ lam4,
    const float* __restrict__ alphav, const float* __restrict__ betav,
    float* __restrict__ out) {
    extern __shared__ char smem[];
    const int tid = threadIdx.x;
    {
        const int4* s2 = (const int4*)g_W2s;
        const int4* s3 = (const int4*)g_W3s;
        int4* d2 = (int4*)(smem + OFF_W2);
        int4* d3 = (int4*)(smem + OFF_W3);
        for (int i = tid; i < 2048; i += 128) { d2[i] = s2[i]; d3[i] = s3[i]; }
        if (tid < 128) {
            ((int4*)(smem + OFF_W1))[tid] = ((const int4*)g_W1p)[tid];
            ((int4*)(smem + OFF_W4))[tid] = ((const int4*)g_W4p)[tid];
            ((float*)(smem + OFF_B1))[tid] = b1v[tid];
            ((float*)(smem + OFF_B2))[tid] = b2v[tid];
            ((float*)(smem + OFF_B3))[tid] = b3v[tid];
        }
        if (tid < 4) {
            ((float*)(smem + OFF_B4))[tid] = b4v[tid];
            ((float*)(smem + OFF_BE))[tid] = betav[tid];
        }
        if (tid < 16) ((float*)(smem + OFF_AL))[tid] = alphav[tid];
    }
    __syncthreads();

    const int w = tid >> 5, t = tid & 31;
    const int gw = blockIdx.x * 4 + w;      // rows [32*gw, 32*gw+32), batches [8gw,8gw+8)
    const int g = t >> 2, q = t & 3, myL = t & 7, hb = (t >> 3) & 1;

    float* xs = (float*)(smem + OFF_SCR) + w * 256;  // x stages [32][4]
    float* Ks = xs + 128;                             // K [32][4]
    const float* sB1 = (const float*)(smem + OFF_B1);
    const float* sB2 = (const float*)(smem + OFF_B2);
    const float* sB3 = (const float*)(smem + OFF_B3);
    const float* sB4 = (const float*)(smem + OFF_B4);
    const float* sAl = (const float*)(smem + OFF_AL);
    const float* sBe = (const float*)(smem + OFF_BE);

    const uint32_t uW1 = (uint32_t)__cvta_generic_to_shared(smem + OFF_W1);
    const uint32_t nOff = (uint32_t)(myL * 256 + (t >> 4) * 2048);
    const uint32_t base2 = (uint32_t)__cvta_generic_to_shared(smem + OFF_W2) + nOff;
    const uint32_t base3 = (uint32_t)__cvta_generic_to_shared(smem + OFF_W3) + nOff;
    const uint32_t base4 = (uint32_t)__cvta_generic_to_shared(smem + OFF_W4) + myL * 256;

    const float aj0 = sAl[q], aj1 = sAl[4 + q], aj2 = sAl[8 + q], aj3 = sAl[12 + q];
    const float l1 = *lam1, l2 = *lam2, l3 = *lam3, l4 = *lam4;
    // lane handles rows r = g + 8j (j=0..3); batch = 8gw + (g>>2) + 2j
    float x0r[4];
#pragma unroll
    for (int j = 0; j < 4; ++j) {
        x0r[j] = X0[(gw * 8 + (g >> 2) + 2 * j) * 4 + q];
        Ks[(g + 8 * j) * 4 + q] = 0.0f;
    }
    __syncwarp();

    unsigned fA0[8][4], fA1[8][4], fB0[8][4], fB1[8][4];

#pragma unroll 1
    for (int it = 0; it < 10; ++it) {
        // X stages: x[r][q] = X0 + dt * sum_i K[r][i]*alpha[i][q]
#pragma unroll
        for (int j = 0; j < 4; ++j) {
            const float* Ka = Ks + (g + 8 * j) * 4;
            xs[(g + 8 * j) * 4 + q] =
                x0r[j] + 0.1f * (Ka[0] * aj0 + Ka[1] * aj1 + Ka[2] * aj2 + Ka[3] * aj3);
        }
        __syncwarp();

        // A-frags for layer 1 (m16 x k8, k cols 4..7 zero), two m-tiles
        unsigned a00 = 0, a01 = 0, a10 = 0, a11 = 0;
        if (q < 2) {
            a00 = packh(xs[g * 4 + 2 * q], xs[g * 4 + 2 * q + 1]);
            a01 = packh(xs[(g + 8) * 4 + 2 * q], xs[(g + 8) * 4 + 2 * q + 1]);
            a10 = packh(xs[(g + 16) * 4 + 2 * q], xs[(g + 16) * 4 + 2 * q + 1]);
            a11 = packh(xs[(g + 24) * 4 + 2 * q], xs[(g + 24) * 4 + 2 * q + 1]);
        }

        // Layer-1 weight fragments (reloaded per-iter: short live range)
        unsigned wv[16];
#pragma unroll
        for (int c = 0; c < 4; ++c)
            ldsm_x4(wv[4 * c], wv[4 * c + 1], wv[4 * c + 2], wv[4 * c + 3],
                    uW1 + (uint32_t)((c * 32 + (t >> 3) * 8 + myL) * 16));

        // Layer 1: 4(->8) -> 128, both m-tiles, f16 accum
#pragma unroll
        for (int jp = 0; jp < 8; ++jp) {
            unsigned bE = packh(sB1[16 * jp + 2 * q], sB1[16 * jp + 2 * q + 1]);
            unsigned bO = packh(sB1[16 * jp + 8 + 2 * q], sB1[16 * jp + 8 + 2 * q + 1]);
            unsigned cE0[2] = {bE, bE};
            unsigned cO0[2] = {bO, bO};
            unsigned cE1[2] = {bE, bE};
            unsigned cO1[2] = {bO, bO};
            mmah8(cE0, a00, a01, wv[2 * jp]);
            mmah8(cO0, a00, a01, wv[2 * jp + 1]);
            mmah8(cE1, a10, a11, wv[2 * jp]);
            mmah8(cO1, a10, a11, wv[2 * jp + 1]);
            fA0[jp][0] = tanh2(cE0[0]);
            fA0[jp][1] = tanh2(cE0[1]);
            fA0[jp][2] = tanh2(cO0[0]);
            fA0[jp][3] = tanh2(cO0[1]);
            fA1[jp][0] = tanh2(cE1[0]);
            fA1[jp][1] = tanh2(cE1[1]);
            fA1[jp][2] = tanh2(cO1[0]);
            fA1[jp][3] = tanh2(cO1[1]);
        }

        layer128m32(fA0, fA1, fB0, fB1, base2, sB2, q, myL, hb);  // layer 2
        layer128m32(fB0, fB1, fA0, fA1, base3, sB3, q, myL, hb);  // layer 3

        // Layer 4: 128 -> 4 (n padded to 8), f16 accum, no tanh
        unsigned c40[2], c41[2];
        {
            unsigned bb = (q < 2) ? packh(sB4[2 * q], sB4[2 * q + 1]) : 0u;
            c40[0] = bb; c40[1] = bb;
            c41[0] = bb; c41[1] = bb;
#pragma unroll
            for (int kc = 0; kc < 8; ++kc) {
                unsigned b0, b1;
                uint32_t sw = (uint32_t)(((((kc << 1) | hb)) ^ myL) << 4);
                ldsm_x2(b0, b1, base4 + sw);
                mmah(c40, fA0[kc], b0, b1);
                mmah(c41, fA1[kc], b0, b1);
            }
        }
        float f0, f1, f2, f3, h0, h1, h2, h3;
        unpackh(f0, f1, c40[0]);   // row g,    cols 2q, 2q+1
        unpackh(f2, f3, c40[1]);   // row g+8
        unpackh(h0, h1, c41[0]);   // row g+16
        unpackh(h2, h3, c41[1]);   // row g+24
        // Hamiltonian vf: swap H col pairs {0,1}<->{2,3} across lanes q=0<->1
        float o0 = __shfl_xor_sync(0xffffffffu, f0, 1);
        float o1 = __shfl_xor_sync(0xffffffffu, f1, 1);
        float o2 = __shfl_xor_sync(0xffffffffu, f2, 1);
        float o3 = __shfl_xor_sync(0xffffffffu, f3, 1);
        float p0 = __shfl_xor_sync(0xffffffffu, h0, 1);
        float p1 = __shfl_xor_sync(0xffffffffu, h1, 1);
        float p2 = __shfl_xor_sync(0xffffffffu, h2, 1);
        float p3 = __shfl_xor_sync(0xffffffffu, h3, 1);
        if (q == 0) {  // K[0],K[1] = -l1*H[2,3] - l2*x[2,3]
            Ks[g * 4 + 0] = -l1 * o0 - l2 * xs[g * 4 + 2];
            Ks[g * 4 + 1] = -l1 * o1 - l2 * xs[g * 4 + 3];
            Ks[(g + 8) * 4 + 0] = -l1 * o2 - l2 * xs[(g + 8) * 4 + 2];
            Ks[(g + 8) * 4 + 1] = -l1 * o3 - l2 * xs[(g + 8) * 4 + 3];
            Ks[(g + 16) * 4 + 0] = -l1 * p0 - l2 * xs[(g + 16) * 4 + 2];
            Ks[(g + 16) * 4 + 1] = -l1 * p1 - l2 * xs[(g + 16) * 4 + 3];
            Ks[(g + 24) * 4 + 0] = -l1 * p2 - l2 * xs[(g + 24) * 4 + 2];
            Ks[(g + 24) * 4 + 1] = -l1 * p3 - l2 * xs[(g + 24) * 4 + 3];
        } else if (q == 1) {  // K[2],K[3] = l3*H[0,1] + l4*x[0,1]
            Ks[g * 4 + 2] = l3 * o0 + l4 * xs[g * 4 + 0];
            Ks[g * 4 + 3] = l3 * o1 + l4 * xs[g * 4 + 1];
            Ks[(g + 8) * 4 + 2] = l3 * o2 + l4 * xs[(g + 8) * 4 + 0];
            Ks[(g + 8) * 4 + 3] = l3 * o3 + l4 * xs[(g + 8) * 4 + 1];
            Ks[(g + 16) * 4 + 2] = l3 * p0 + l4 * xs[(g + 16) * 4 + 0];
            Ks[(g + 16) * 4 + 3] = l3 * p1 + l4 * xs[(g + 16) * 4 + 1];
            Ks[(g + 24) * 4 + 2] = l3 * p2 + l4 * xs[(g + 24) * 4 + 0];
            Ks[(g + 24) * 4 + 3] = l3 * p3 + l4 * xs[(g + 24) * 4 + 1];
        }
        __syncwarp();
    }

    // Final combine: X1 = X0 + dt * sum_s beta[s]*K[b][s][:]; 8 batches/warp
    {
        int bb = t >> 2, c = t & 3;
        float s = sBe[0] * Ks[(bb * 4 + 0) * 4 + c] + sBe[1] * Ks[(bb * 4 + 1) * 4 + c] +
                  sBe[2] * Ks[(bb * 4 + 2) * 4 + c] + sBe[3] * Ks[(bb * 4 + 3) * 4 + c];
        int gi = (gw * 8 + bb) * 4 + c;
        out[gi] = X0[gi] + 0.1f * s;
    }
}

extern "C" void kernel_launch(void* const* d_in, const int* in_sizes, int n_in,
                              void* d_out, int out_size) {
    const float* X0    = (const float*)d_in[0];
    const float* W1    = (const float*)d_in[1];
    const float* b1    = (const float*)d_in[2];
    const float* W2    = (const float*)d_in[3];
    const float* b2    = (const float*)d_in[4];
    const float* W3    = (const float*)d_in[5];
    const float* b3    = (const float*)d_in[6];
    const float* W4    = (const float*)d_in[7];
    const float* b4    = (const float*)d_in[8];
    const float* lam1  = (const float*)d_in[9];
    const float* lam2  = (const float*)d_in[10];
    const float* lam3  = (const float*)d_in[11];
    const float* lam4  = (const float*)d_in[12];
    const float* alpha = (const float*)d_in[13];
    const float* beta  = (const float*)d_in[14];

    cudaFuncSetAttribute(pinns_main, cudaFuncAttributeMaxDynamicSharedMemorySize, SMEM_TOTAL);
    pinns_prep<<<64, 256>>>(W1, W2, W3, W4);
    pinns_main<<<2048, 128, SMEM_TOTAL>>>(X0, b1, b2, b3, b4,
                                          lam1, lam2, lam3, lam4,
                                          alpha, beta, (float*)d_out);
}